// round 16
// baseline (speedup 1.0000x reference)
#include <cuda_runtime.h>
#include <cuda_bf16.h>
#include <math.h>
#include <stdint.h>

#define NROWS 50000
#define DIN   1024
#define DH    512
#define DA    256
#define KSEL  8
#define MBLK  391             // row blocks of 128
#define NCAND (MBLK * 8)      // 3128

#define BM 128
#define BN 128
#define BK 32

#define ROWB      80
#define OFF_AHI   0
#define OFF_ALO   10240
#define OFF_BHI   20480
#define OFF_BLO   30720
#define STAGEB    40960
#define OFF_XRAW  81920
#define XSTAGE    16384
#define SMEM_GEMM (OFF_XRAW + 2 * XSTAGE)   // 112 KB -> 2 CTAs/SM

#define XSW(row, seg) ((row) * 128 + ((seg) ^ (((row) & 7) << 4)))

// ---------------- scratch (static device allocations only) ----------------
__device__ __nv_bfloat16  g_hh_hi[(size_t)NROWS * DH];
__device__ __nv_bfloat16  g_hh_lo[(size_t)NROWS * DH];
__device__ __nv_bfloat16  g_w1_hi[(size_t)DH * DIN];
__device__ __nv_bfloat16  g_w1_lo[(size_t)DH * DIN];
__device__ __nv_bfloat16  g_wab_hi[(size_t)DH * DH];
__device__ __nv_bfloat16  g_wab_lo[(size_t)DH * DH];
__device__ float          g_part[4][NROWS];
__device__ float          g_cls_part[4][NROWS][2];
__device__ float          g_red[MBLK][4];
__device__ float          g_ctv[NCAND];
__device__ int            g_cti[NCAND];
__device__ float          g_cbv[NCAND];
__device__ int            g_cbi[NCAND];
__device__ int            g_cnt[MBLK];
__device__ int            g_ids[16];

// ============================ helpers ======================================
__device__ __forceinline__ uint32_t smem_u32(const void* p) {
    uint32_t a;
    asm("{ .reg .u64 t; cvta.to.shared.u64 t, %1; cvt.u32.u64 %0, t; }" : "=r"(a) : "l"(p));
    return a;
}
__device__ __forceinline__ void split2(float x, float y, uint32_t& hi, uint32_t& lo)
{
    __nv_bfloat16 hx = __float2bfloat16(x);
    __nv_bfloat16 hy = __float2bfloat16(y);
    __nv_bfloat16 lx = __float2bfloat16(x - __bfloat162float(hx));
    __nv_bfloat16 ly = __float2bfloat16(y - __bfloat162float(hy));
    hi = (uint32_t)__bfloat16_as_ushort(hx) | ((uint32_t)__bfloat16_as_ushort(hy) << 16);
    lo = (uint32_t)__bfloat16_as_ushort(lx) | ((uint32_t)__bfloat16_as_ushort(ly) << 16);
}
__device__ __forceinline__ void mma_bf16(float* d, const uint32_t* a, const uint32_t* b)
{
    asm("mma.sync.aligned.m16n8k16.row.col.f32.bf16.bf16.f32 "
        "{%0,%1,%2,%3}, {%4,%5,%6,%7}, {%8,%9}, {%0,%1,%2,%3};"
        : "+f"(d[0]), "+f"(d[1]), "+f"(d[2]), "+f"(d[3])
        : "r"(a[0]), "r"(a[1]), "r"(a[2]), "r"(a[3]), "r"(b[0]), "r"(b[1]));
}
#define LDSM_X4(r0, r1, r2, r3, addr) \
    asm volatile("ldmatrix.sync.aligned.m8n8.x4.shared.b16 {%0,%1,%2,%3}, [%4];" \
                 : "=r"(r0), "=r"(r1), "=r"(r2), "=r"(r3) : "r"(addr))
#define CP_ASYNC16(dst, src, sz) \
    asm volatile("cp.async.cg.shared.global [%0], [%1], 16, %2;" \
                 :: "r"(dst), "l"(src), "r"(sz))
#define CP_COMMIT()  asm volatile("cp.async.commit_group;" ::: "memory")
#define CP_WAIT(n)   asm volatile("cp.async.wait_group %0;" :: "n"(n) : "memory")

__device__ __forceinline__ float fast_sigmoid(float x) {
    return __fdividef(1.f, 1.f + __expf(-x));
}
__device__ __forceinline__ float fast_tanh(float x) {
    return __fdividef(2.f, 1.f + __expf(-2.f * x)) - 1.f;
}
__device__ __forceinline__ bool tk_better(float v1, int i1, float v2, int i2, bool mx)
{
    if (mx) return (v1 > v2) || (v1 == v2 && i1 < i2);
    return (v1 < v2) || (v1 == v2 && i1 < i2);
}

// ================= weight convert kernel (+ counter reset) =================
#define NBW1 (DH * DIN / 4 / 256)               // 512
#define NBWAB (DH * DH / 4 / 256)               // 256
__global__ __launch_bounds__(256) void conv_w_kernel(
    const float* __restrict__ fcW,
    const float* __restrict__ Wa, const float* __restrict__ Wb,
    __nv_bfloat16* __restrict__ w1hi, __nv_bfloat16* __restrict__ w1lo)
{
    int b = blockIdx.x;
    if (b == 0) {
        for (int i = threadIdx.x; i < MBLK; i += 256) g_cnt[i] = 0;
    }
    if (b < NBW1) {
        int i = b * 256 + threadIdx.x;
        float4 v = ((const float4*)fcW)[i];
        uint32_t h0, l0, h1, l1;
        split2(v.x, v.y, h0, l0);
        split2(v.z, v.w, h1, l1);
        ((uint2*)w1hi)[i] = make_uint2(h0, h1);
        ((uint2*)w1lo)[i] = make_uint2(l0, l1);
    } else {
        int i = (b - NBW1) * 256 + threadIdx.x;
        int elem = i * 4;
        int row = elem / DH;
        int col = elem % DH;
        const float* src = (row < DA) ? &Wa[(size_t)row * DH + col]
                                      : &Wb[(size_t)(row - DA) * DH + col];
        float4 v = *(const float4*)src;
        uint32_t h0, l0, h1, l1;
        split2(v.x, v.y, h0, l0);
        split2(v.z, v.w, h1, l1);
        ((uint2*)g_wab_hi)[i] = make_uint2(h0, h1);
        ((uint2*)g_wab_lo)[i] = make_uint2(l0, l1);
    }
}

// ===========================================================================
// 3xBF16 split GEMM (frozen R8 mainloop).
//  mode 0 (gemm1): A = raw fp32 X + in-kernel split; epilogue -> hh + cls part
//  mode 1 (gemm2): A_raw partials; LAST CTA per row-block finalizes:
//                  Araw/IS outputs + softmax partials + block top8/bottom8
// ===========================================================================
__global__ __launch_bounds__(256, 2) void gemm_mma_kernel(
    const float* __restrict__ Xraw,
    const __nv_bfloat16* __restrict__ Ahi, const __nv_bfloat16* __restrict__ Alo,
    const __nv_bfloat16* __restrict__ Bhi, const __nv_bfloat16* __restrict__ Blo,
    const float* __restrict__ bias,
    const float* __restrict__ abv, const float* __restrict__ bbv,
    const float* __restrict__ cWv, const float* __restrict__ clsW,
    const float* __restrict__ cb2, const float* __restrict__ clsb2,
    float* __restrict__ Araw, float* __restrict__ IS,
    int K, int mode)
{
    extern __shared__ char smem[];
    const uint32_t sbase = smem_u32(smem);

    const int tid    = threadIdx.x;
    const int wid    = tid >> 5;
    const int lane   = tid & 31;
    const int warp_m = wid & 1;
    const int warp_n = wid >> 1;
    const int g      = lane >> 2;
    const int t      = lane & 3;
    const int bx     = blockIdx.x;
    const int row0   = blockIdx.y * BM;
    const int col0   = (mode == 0) ? bx * BN : bx * 64;

    const int mat   = lane >> 3;
    const int rowin = lane & 7;
    const int rowA  = warp_m * 64 + ((mat & 1) << 3) + rowin;
    const int kA    = (mat >> 1) << 3;
    const int rowB0 = warp_n * 32 + ((mat >> 1) << 3) + rowin;
    const int kB    = (mat & 1) << 3;

    const int frow = tid >> 2;
    const int fseg = (tid & 3) * 16;

    float acc[4][4][4];
#pragma unroll
    for (int mt = 0; mt < 4; mt++)
#pragma unroll
        for (int nt = 0; nt < 4; nt++)
#pragma unroll
            for (int e = 0; e < 4; e++) acc[mt][nt][e] = 0.f;

    const int KT = K / BK;

    auto fill = [&](int kt, int s) {
        if (mode == 0) {
            uint32_t xb = sbase + OFF_XRAW + s * XSTAGE;
#pragma unroll
            for (int i = 0; i < 4; i++) {
                int c   = tid + 256 * i;
                int r   = c >> 3;
                int seg = (c & 7) * 16;
                int gr  = row0 + r;
                uint32_t ok = (gr < NROWS) ? 16u : 0u;
                const float* src = &Xraw[(size_t)min(gr, NROWS - 1) * K + kt * BK + (seg >> 2)];
                CP_ASYNC16(xb + XSW(r, seg), (const char*)src, ok);
            }
            uint32_t sb = sbase + s * STAGEB;
            int kc = kt * BK + (fseg >> 1);
#pragma unroll
            for (int i = 0; i < 2; i++) {
                int r = frow + 64 * i;
                int brow = col0 + r;
                size_t bi = (size_t)brow * K + kc;
                uint32_t d = sb + r * ROWB + fseg;
                CP_ASYNC16(d + OFF_BHI, (const char*)&Bhi[bi], 16u);
                CP_ASYNC16(d + OFF_BLO, (const char*)&Blo[bi], 16u);
            }
        } else {
            uint32_t sb = sbase + s * STAGEB;
            int kc = kt * BK + (fseg >> 1);
#pragma unroll
            for (int i = 0; i < 2; i++) {
                int r = frow + 64 * i;
                int gr = row0 + r;
                uint32_t ok = (gr < NROWS) ? 16u : 0u;
                size_t gi = (size_t)min(gr, NROWS - 1) * K + kc;
                uint32_t d = sb + r * ROWB + fseg;
                CP_ASYNC16(d + OFF_AHI, (const char*)&Ahi[gi], ok);
                CP_ASYNC16(d + OFF_ALO, (const char*)&Alo[gi], ok);
                int w = r >> 5, ii = r & 31;
                int j = col0 + (w << 4) + (ii & 15);
                int brow = (ii < 16) ? j : j + DA;
                size_t bi = (size_t)brow * K + kc;
                CP_ASYNC16(d + OFF_BHI, (const char*)&Bhi[bi], 16u);
                CP_ASYNC16(d + OFF_BLO, (const char*)&Blo[bi], 16u);
            }
        }
    };

    fill(0, 0);
    CP_COMMIT();

    for (int kt = 0; kt < KT; kt++) {
        int cur = kt & 1;
        if (kt + 1 < KT) {
            fill(kt + 1, cur ^ 1);
            CP_COMMIT();
            CP_WAIT(1);
        } else {
            CP_WAIT(0);
        }
        __syncthreads();

        uint32_t sb = sbase + cur * STAGEB;

        if (mode == 0) {
            int r  = tid >> 1;
            int hf = tid & 1;
            const char* xbase = smem + OFF_XRAW + cur * XSTAGE;
            float4 v0 = *(const float4*)(xbase + XSW(r, hf * 64 + 0));
            float4 v1 = *(const float4*)(xbase + XSW(r, hf * 64 + 16));
            float4 v2 = *(const float4*)(xbase + XSW(r, hf * 64 + 32));
            float4 v3 = *(const float4*)(xbase + XSW(r, hf * 64 + 48));
            uint32_t h0, l0, h1, l1, h2, l2, h3, l3, h4, l4, h5, l5, h6, l6, h7, l7;
            split2(v0.x, v0.y, h0, l0); split2(v0.z, v0.w, h1, l1);
            split2(v1.x, v1.y, h2, l2); split2(v1.z, v1.w, h3, l3);
            split2(v2.x, v2.y, h4, l4); split2(v2.z, v2.w, h5, l5);
            split2(v3.x, v3.y, h6, l6); split2(v3.z, v3.w, h7, l7);
            char* dA = smem + cur * STAGEB + r * ROWB + hf * 32;
            *(uint4*)(dA + OFF_AHI)      = make_uint4(h0, h1, h2, h3);
            *(uint4*)(dA + OFF_AHI + 16) = make_uint4(h4, h5, h6, h7);
            *(uint4*)(dA + OFF_ALO)      = make_uint4(l0, l1, l2, l3);
            *(uint4*)(dA + OFF_ALO + 16) = make_uint4(l4, l5, l6, l7);
            __syncthreads();
        }

#pragma unroll
        for (int ks = 0; ks < BK; ks += 16) {
            uint32_t bh[4][2], bl[4][2];
#pragma unroll
            for (int p = 0; p < 2; p++) {
                uint32_t ab_ = sb + (rowB0 + p * 16) * ROWB + (ks + kB) * 2;
                LDSM_X4(bh[2 * p][0], bh[2 * p][1], bh[2 * p + 1][0], bh[2 * p + 1][1],
                        ab_ + OFF_BHI);
                LDSM_X4(bl[2 * p][0], bl[2 * p][1], bl[2 * p + 1][0], bl[2 * p + 1][1],
                        ab_ + OFF_BLO);
            }
#pragma unroll
            for (int mt = 0; mt < 4; mt++) {
                uint32_t aa = sb + (rowA + mt * 16) * ROWB + (ks + kA) * 2;
                uint32_t ah[4], al[4];
                LDSM_X4(ah[0], ah[1], ah[2], ah[3], aa + OFF_AHI);
                LDSM_X4(al[0], al[1], al[2], al[3], aa + OFF_ALO);
#pragma unroll
                for (int nt = 0; nt < 4; nt++) mma_bf16(acc[mt][nt], ah, bh[nt]);
#pragma unroll
                for (int nt = 0; nt < 4; nt++) mma_bf16(acc[mt][nt], ah, bl[nt]);
#pragma unroll
                for (int nt = 0; nt < 4; nt++) mma_bf16(acc[mt][nt], al, bh[nt]);
            }
        }
        __syncthreads();
    }

    if (mode == 0) {
        float* sc0 = (float*)smem;
        float* sc1 = (float*)smem + 512;
#pragma unroll
        for (int mt = 0; mt < 4; mt++) {
            int r0 = row0 + warp_m * 64 + mt * 16 + g;
            int r1 = r0 + 8;
            float p00 = 0.f, p01 = 0.f, p10 = 0.f, p11 = 0.f;
#pragma unroll
            for (int nt = 0; nt < 4; nt++) {
                int c = col0 + warp_n * 32 + nt * 8 + 2 * t;
                float b0 = __ldg(&bias[c]), b1 = __ldg(&bias[c + 1]);
                float v0 = fmaxf(acc[mt][nt][0] + b0, 0.f);
                float v1 = fmaxf(acc[mt][nt][1] + b1, 0.f);
                float v2 = fmaxf(acc[mt][nt][2] + b0, 0.f);
                float v3 = fmaxf(acc[mt][nt][3] + b1, 0.f);
                float w00 = __ldg(&clsW[c]),      w01 = __ldg(&clsW[c + 1]);
                float w10 = __ldg(&clsW[DH + c]), w11 = __ldg(&clsW[DH + c + 1]);
                p00 += v0 * w00 + v1 * w01;
                p01 += v0 * w10 + v1 * w11;
                p10 += v2 * w00 + v3 * w01;
                p11 += v2 * w10 + v3 * w11;
                uint32_t hh, ll;
                if (r0 < NROWS) {
                    split2(v0, v1, hh, ll);
                    *(uint32_t*)&g_hh_hi[(size_t)r0 * DH + c] = hh;
                    *(uint32_t*)&g_hh_lo[(size_t)r0 * DH + c] = ll;
                }
                if (r1 < NROWS) {
                    split2(v2, v3, hh, ll);
                    *(uint32_t*)&g_hh_hi[(size_t)r1 * DH + c] = hh;
                    *(uint32_t*)&g_hh_lo[(size_t)r1 * DH + c] = ll;
                }
            }
            p00 += __shfl_xor_sync(0xffffffffu, p00, 1);
            p00 += __shfl_xor_sync(0xffffffffu, p00, 2);
            p01 += __shfl_xor_sync(0xffffffffu, p01, 1);
            p01 += __shfl_xor_sync(0xffffffffu, p01, 2);
            p10 += __shfl_xor_sync(0xffffffffu, p10, 1);
            p10 += __shfl_xor_sync(0xffffffffu, p10, 2);
            p11 += __shfl_xor_sync(0xffffffffu, p11, 1);
            p11 += __shfl_xor_sync(0xffffffffu, p11, 2);
            if (t == 0) {
                int rl = warp_m * 64 + mt * 16 + g;
                sc0[rl * 4 + warp_n] = p00;
                sc1[rl * 4 + warp_n] = p01;
                sc0[(rl + 8) * 4 + warp_n] = p10;
                sc1[(rl + 8) * 4 + warp_n] = p11;
            }
        }
        __syncthreads();
        if (tid < 128) {
            int grow = row0 + tid;
            if (grow < NROWS) {
                g_cls_part[bx][grow][0] = sc0[tid * 4 + 0] + sc0[tid * 4 + 1] +
                                          sc0[tid * 4 + 2] + sc0[tid * 4 + 3];
                g_cls_part[bx][grow][1] = sc1[tid * 4 + 0] + sc1[tid * 4 + 1] +
                                          sc1[tid * 4 + 2] + sc1[tid * 4 + 3];
            }
        }
    } else {
        // ---- gemm2 epilogue: A_raw partial, then last-CTA finalize ----
        float* spart = (float*)smem;   // [128][4]
#pragma unroll
        for (int mt = 0; mt < 4; mt++) {
            float s0 = 0.f, s1 = 0.f;
#pragma unroll
            for (int nt = 0; nt < 2; nt++) {
                int j = col0 + warp_n * 16 + nt * 8 + 2 * t;
                float ab0 = __ldg(&abv[j]), ab1 = __ldg(&abv[j + 1]);
                float bb0 = __ldg(&bbv[j]), bb1 = __ldg(&bbv[j + 1]);
                float c0  = __ldg(&cWv[j]), c1  = __ldg(&cWv[j + 1]);
                s0 += c0 * fast_tanh(acc[mt][nt][0] + ab0) * fast_sigmoid(acc[mt][nt + 2][0] + bb0);
                s0 += c1 * fast_tanh(acc[mt][nt][1] + ab1) * fast_sigmoid(acc[mt][nt + 2][1] + bb1);
                s1 += c0 * fast_tanh(acc[mt][nt][2] + ab0) * fast_sigmoid(acc[mt][nt + 2][2] + bb0);
                s1 += c1 * fast_tanh(acc[mt][nt][3] + ab1) * fast_sigmoid(acc[mt][nt + 2][3] + bb1);
            }
            s0 += __shfl_xor_sync(0xffffffffu, s0, 1);
            s0 += __shfl_xor_sync(0xffffffffu, s0, 2);
            s1 += __shfl_xor_sync(0xffffffffu, s1, 1);
            s1 += __shfl_xor_sync(0xffffffffu, s1, 2);
            if (t == 0) {
                int rl = warp_m * 64 + mt * 16 + g;
                spart[rl * 4 + warp_n] = s0;
                spart[(rl + 8) * 4 + warp_n] = s1;
            }
        }
        __syncthreads();
        if (tid < 128) {
            int grow = row0 + tid;
            if (grow < NROWS) {
                g_part[bx][grow] = spart[tid * 4 + 0] + spart[tid * 4 + 1] +
                                   spart[tid * 4 + 2] + spart[tid * 4 + 3];
            }
        }
        __syncthreads();

        int* flag = (int*)(smem + 2560);
        if (tid == 0) {
            __threadfence();
            int old = atomicAdd(&g_cnt[blockIdx.y], 1);
            *flag = (old == 3) ? 1 : 0;
        }
        __syncthreads();
        if (!(*flag)) return;
        __threadfence();

        // ---- finalize this 128-row block ----
        int rb = blockIdx.y;
        float* wred = (float*)(smem + 2576);   // [4][4]
        float* cwv2 = (float*)(smem + 2704);   // 32
        int*   cwi2 = (int*)  (smem + 2832);   // 32
        int grow = row0 + tid;
        bool valid = (tid < 128) && (grow < NROWS);
        float a = -INFINITY, is0 = 0.f, is1 = 0.f;
        if (valid) {
            a = cb2[0] + g_part[0][grow] + g_part[1][grow] +
                         g_part[2][grow] + g_part[3][grow];
            Araw[grow] = a;
            is0 = clsb2[0] + g_cls_part[0][grow][0] + g_cls_part[1][grow][0] +
                             g_cls_part[2][grow][0] + g_cls_part[3][grow][0];
            is1 = clsb2[1] + g_cls_part[0][grow][1] + g_cls_part[1][grow][1] +
                             g_cls_part[2][grow][1] + g_cls_part[3][grow][1];
            IS[(size_t)grow * 2 + 0] = is0;
            IS[(size_t)grow * 2 + 1] = is1;
        }

        if (tid < 128) {
            float wm = a;
#pragma unroll
            for (int m = 16; m > 0; m >>= 1)
                wm = fmaxf(wm, __shfl_xor_sync(0xffffffffu, wm, m));
            if (lane == 0) wred[wid * 4 + 0] = wm;
        }
        __syncthreads();
        float bm = fmaxf(fmaxf(wred[0], wred[4]), fmaxf(wred[8], wred[12]));
        float e  = valid ? expf(a - bm) : 0.f;
        float p0 = e * is0, p1 = e * is1;
        if (tid < 128) {
#pragma unroll
            for (int m = 16; m > 0; m >>= 1) {
                e  += __shfl_xor_sync(0xffffffffu, e,  m);
                p0 += __shfl_xor_sync(0xffffffffu, p0, m);
                p1 += __shfl_xor_sync(0xffffffffu, p1, m);
            }
            if (lane == 0) { wred[wid * 4 + 1] = e; wred[wid * 4 + 2] = p0; wred[wid * 4 + 3] = p1; }
        }
        __syncthreads();
        if (tid == 0) {
            float se = 0.f, s0 = 0.f, s1 = 0.f;
#pragma unroll
            for (int i = 0; i < 4; i++) {
                se += wred[i * 4 + 1]; s0 += wred[i * 4 + 2]; s1 += wred[i * 4 + 3];
            }
            g_red[rb][0] = bm; g_red[rb][1] = se; g_red[rb][2] = s0; g_red[rb][3] = s1;
        }

        // selection: warps 0-3 local top/bottom 8 -> warp 0 merges 32 -> 8
        for (int pass = 0; pass < 2; pass++) {
            bool mx = (pass == 0);
            if (tid < 128) {
                float cv = valid ? a : (mx ? -INFINITY : INFINITY);
                int   ci = valid ? grow : 0x7fffffff;
                for (int it = 0; it < 8; it++) {
                    float bv = cv;
                    int   bi = ci;
#pragma unroll
                    for (int m = 16; m > 0; m >>= 1) {
                        float ov = __shfl_xor_sync(0xffffffffu, bv, m);
                        int   oi = __shfl_xor_sync(0xffffffffu, bi, m);
                        if (tk_better(ov, oi, bv, bi, mx)) { bv = ov; bi = oi; }
                    }
                    if (lane == it) { cwv2[wid * 8 + it] = bv; cwi2[wid * 8 + it] = bi; }
                    if (ci == bi) cv = mx ? -INFINITY : INFINITY;
                }
            }
            __syncthreads();
            if (wid == 0) {
                float e0 = cwv2[lane];
                int   i0 = cwi2[lane];
                for (int it = 0; it < 8; it++) {
                    float bv = e0; int bi = i0;
#pragma unroll
                    for (int m = 16; m > 0; m >>= 1) {
                        float ov = __shfl_xor_sync(0xffffffffu, bv, m);
                        int   oi = __shfl_xor_sync(0xffffffffu, bi, m);
                        if (tk_better(ov, oi, bv, bi, mx)) { bv = ov; bi = oi; }
                    }
                    if (lane == 0) {
                        if (mx) { g_ctv[rb * 8 + it] = bv; g_cti[rb * 8 + it] = bi; }
                        else    { g_cbv[rb * 8 + it] = bv; g_cbi[rb * 8 + it] = bi; }
                    }
                    if (i0 == bi) e0 = mx ? -INFINITY : INFINITY;
                }
            }
            __syncthreads();
        }
    }
}

// ---------------------------------------------------------------------------
// tail: preds finalize + candidate merge (bitonic tree) + instance loss
// ---------------------------------------------------------------------------
__global__ __launch_bounds__(512) void tail_kernel(
    const float* __restrict__ iW, const float* __restrict__ ib,
    float* __restrict__ preds, float* __restrict__ loss)
{
    __shared__ float rm[512], r0[512], r1[512], r2[512];
    __shared__ float pv[512 * 8];
    __shared__ int   pi[512 * 8];
    __shared__ int   sel[16];
    __shared__ float ls[16];
    int tid = threadIdx.x;

    float m = (tid < MBLK) ? g_red[tid][0] : -INFINITY;
    rm[tid] = m;
    __syncthreads();
    for (int s = 256; s > 0; s >>= 1) {
        if (tid < s) rm[tid] = fmaxf(rm[tid], rm[tid + s]);
        __syncthreads();
    }
    float M = rm[0];
    __syncthreads();
    float se = 0.f, s0 = 0.f, s1 = 0.f;
    if (tid < MBLK) {
        float w = expf(g_red[tid][0] - M);
        se = w * g_red[tid][1];
        s0 = w * g_red[tid][2];
        s1 = w * g_red[tid][3];
    }
    r0[tid] = se; r1[tid] = s0; r2[tid] = s1;
    __syncthreads();
    for (int s = 256; s > 0; s >>= 1) {
        if (tid < s) {
            r0[tid] += r0[tid + s];
            r1[tid] += r1[tid + s];
            r2[tid] += r2[tid + s];
        }
        __syncthreads();
    }
    if (tid == 0) {
        preds[0] = r1[0] / r0[0];
        preds[1] = r2[0] / r0[0];
    }
    __syncthreads();

    for (int pass = 0; pass < 2; pass++) {
        bool mx = (pass == 0);
        float tv[8];
        int   ti[8];
        float pad = mx ? -INFINITY : INFINITY;
#pragma unroll
        for (int j = 0; j < 8; j++) { tv[j] = pad; ti[j] = 0x7fffffff; }
        for (int i = tid; i < NCAND; i += 512) {
            float v = mx ? g_ctv[i] : g_cbv[i];
            int   idx = mx ? g_cti[i] : g_cbi[i];
            if (tk_better(v, idx, tv[7], ti[7], mx)) {
                int p = 7;
#pragma unroll
                for (int q = 7; q > 0; q--) {
                    if (tk_better(v, idx, tv[q - 1], ti[q - 1], mx)) {
                        tv[q] = tv[q - 1]; ti[q] = ti[q - 1]; p = q - 1;
                    }
                }
                tv[p] = v; ti[p] = idx;
            }
        }
#pragma unroll
        for (int j = 0; j < 8; j++) { pv[tid * 8 + j] = tv[j]; pi[tid * 8 + j] = ti[j]; }
        __syncthreads();

        for (int s = 256; s > 0; s >>= 1) {
            if (tid < s) {
                float cv[16]; int ci[16];
#pragma unroll
                for (int j = 0; j < 8; j++) {
                    cv[j] = pv[tid * 8 + j];
                    ci[j] = pi[tid * 8 + j];
                    cv[8 + j] = pv[(tid + s) * 8 + 7 - j];
                    ci[8 + j] = pi[(tid + s) * 8 + 7 - j];
                }
#pragma unroll
                for (int st = 8; st >= 1; st >>= 1) {
#pragma unroll
                    for (int i = 0; i < 16; i++) {
                        if (!(i & st)) {
                            int k = i | st;
                            if (tk_better(cv[k], ci[k], cv[i], ci[i], mx)) {
                                float fv = cv[i]; cv[i] = cv[k]; cv[k] = fv;
                                int   fi = ci[i]; ci[i] = ci[k]; ci[k] = fi;
                            }
                        }
                    }
                }
#pragma unroll
                for (int j = 0; j < 8; j++) { pv[tid * 8 + j] = cv[j]; pi[tid * 8 + j] = ci[j]; }
            }
            __syncthreads();
        }
        if (tid < 8) { sel[pass * 8 + tid] = pi[tid]; g_ids[pass * 8 + tid] = pi[tid]; }
        __syncthreads();
    }

    int w    = tid >> 5;
    int lane = tid & 31;
    int id   = sel[w];
    const __nv_bfloat16* hhi = &g_hh_hi[(size_t)id * DH];
    const __nv_bfloat16* hlo = &g_hh_lo[(size_t)id * DH];
    float c0 = 0.f, c1 = 0.f;
    for (int k = lane * 4; k < DH; k += 128) {
        uint2 ph = *(const uint2*)&hhi[k];
        uint2 pl = *(const uint2*)&hlo[k];
        float h0 = __bfloat162float(__ushort_as_bfloat16((unsigned short)(ph.x & 0xffff)))
                 + __bfloat162float(__ushort_as_bfloat16((unsigned short)(pl.x & 0xffff)));
        float h1 = __bfloat162float(__ushort_as_bfloat16((unsigned short)(ph.x >> 16)))
                 + __bfloat162float(__ushort_as_bfloat16((unsigned short)(pl.x >> 16)));
        float h2 = __bfloat162float(__ushort_as_bfloat16((unsigned short)(ph.y & 0xffff)))
                 + __bfloat162float(__ushort_as_bfloat16((unsigned short)(pl.y & 0xffff)));
        float h3 = __bfloat162float(__ushort_as_bfloat16((unsigned short)(ph.y >> 16)))
                 + __bfloat162float(__ushort_as_bfloat16((unsigned short)(pl.y >> 16)));
        float4 w0 = *(const float4*)&iW[k];
        float4 w1 = *(const float4*)&iW[DH + k];
        c0 += h0 * w0.x + h1 * w0.y + h2 * w0.z + h3 * w0.w;
        c1 += h0 * w1.x + h1 * w1.y + h2 * w1.z + h3 * w1.w;
    }
#pragma unroll
    for (int mk = 16; mk > 0; mk >>= 1) {
        c0 += __shfl_xor_sync(0xffffffffu, c0, mk);
        c1 += __shfl_xor_sync(0xffffffffu, c1, mk);
    }
    if (lane == 0) {
        float l0 = c0 + ib[0], l1 = c1 + ib[1];
        float mm  = fmaxf(l0, l1);
        float lse = mm + logf(expf(l0 - mm) + expf(l1 - mm));
        float lt  = (w < KSEL) ? l1 : l0;
        ls[w] = lse - lt;
    }
    __syncthreads();
    if (tid == 0) {
        float tsum = 0.f;
        for (int i = 0; i < 16; i++) tsum += ls[i];
        loss[0] = tsum / 16.f;
    }
}

// ---------------------------------------------------------------------------
extern "C" void kernel_launch(void* const* d_in, const int* in_sizes, int n_in,
                              void* d_out, int out_size)
{
    const float* h     = (const float*)d_in[0];
    const float* fcW   = (const float*)d_in[1];
    const float* fcb   = (const float*)d_in[2];
    const float* aW    = (const float*)d_in[3];
    const float* abv   = (const float*)d_in[4];
    const float* bW    = (const float*)d_in[5];
    const float* bbv   = (const float*)d_in[6];
    const float* cWv   = (const float*)d_in[7];
    const float* cbv   = (const float*)d_in[8];
    const float* clsW  = (const float*)d_in[9];
    const float* clsb  = (const float*)d_in[10];
    const float* instW = (const float*)d_in[11];
    const float* instb = (const float*)d_in[12];

    float* out   = (float*)d_out;
    float* preds = out;
    float* IS    = out + 2;
    float* Araw  = out + 2 + 2 * NROWS;
    float* loss  = out + 2 + 3 * NROWS;

    static int inited = 0;
    if (!inited) {
        cudaFuncSetAttribute(gemm_mma_kernel,
                             cudaFuncAttributeMaxDynamicSharedMemorySize, SMEM_GEMM);
        inited = 1;
    }

    __nv_bfloat16 *w1hi, *w1lo, *wabhi, *wablo, *hhhi, *hhlo;
    cudaGetSymbolAddress((void**)&w1hi,  g_w1_hi);
    cudaGetSymbolAddress((void**)&w1lo,  g_w1_lo);
    cudaGetSymbolAddress((void**)&wabhi, g_wab_hi);
    cudaGetSymbolAddress((void**)&wablo, g_wab_lo);
    cudaGetSymbolAddress((void**)&hhhi,  g_hh_hi);
    cudaGetSymbolAddress((void**)&hhlo,  g_hh_lo);

    conv_w_kernel<<<NBW1 + NBWAB, 256>>>(fcW, aW, bW, w1hi, w1lo);

    dim3 grid(4, MBLK);

    // gemm1: A = raw fp32 X (in-kernel split), B = fcW hi/lo
    gemm_mma_kernel<<<grid, 256, SMEM_GEMM>>>(h, (const __nv_bfloat16*)0,
                                              (const __nv_bfloat16*)0,
                                              w1hi, w1lo, fcb,
                                              (const float*)0, (const float*)0,
                                              (const float*)0, clsW,
                                              (const float*)0, (const float*)0,
                                              (float*)0, (float*)0, DIN, 0);

    // gemm2: A = hh hi/lo; fused A_raw partials + last-CTA finalize
    gemm_mma_kernel<<<grid, 256, SMEM_GEMM>>>((const float*)0, hhhi, hhlo,
                                              wabhi, wablo,
                                              (const float*)0, abv, bbv, cWv,
                                              (const float*)0,
                                              cbv, clsb, Araw, IS, DH, 1);

    tail_kernel<<<1, 512>>>(instW, instb, preds, loss);
}

// round 17
// speedup vs baseline: 1.0223x; 1.0223x over previous
#include <cuda_runtime.h>
#include <cuda_bf16.h>
#include <math.h>
#include <stdint.h>

#define NROWS 50000
#define DIN   1024
#define DH    512
#define DA    256
#define KSEL  8
#define NB_POST 196   // ceil(50000/256)
#define NCAND (NB_POST * 8)   // 1568
#define NC_PER_WARP (NCAND / 16)  // 98

#define BM 128
#define BN 128
#define BK 32

#define ROWB      80
#define OFF_AHI   0
#define OFF_ALO   10240
#define OFF_BHI   20480
#define OFF_BLO   30720
#define STAGEB    40960
#define OFF_XRAW  81920
#define XSTAGE    16384
#define SMEM_GEMM (OFF_XRAW + 2 * XSTAGE)   // 112 KB -> 2 CTAs/SM

#define XSW(row, seg) ((row) * 128 + ((seg) ^ (((row) & 7) << 4)))

// ---------------- scratch (static device allocations only) ----------------
__device__ __nv_bfloat16  g_hh_hi[(size_t)NROWS * DH];
__device__ __nv_bfloat16  g_hh_lo[(size_t)NROWS * DH];
__device__ __nv_bfloat16  g_w1_hi[(size_t)DH * DIN];
__device__ __nv_bfloat16  g_w1_lo[(size_t)DH * DIN];
__device__ __nv_bfloat16  g_wab_hi[(size_t)DH * DH];
__device__ __nv_bfloat16  g_wab_lo[(size_t)DH * DH];
__device__ float          g_part[4][NROWS];
__device__ float          g_cls_part[4][NROWS][2];
__device__ float          g_red[NB_POST][4];
__device__ float          g_ctv[NCAND];
__device__ int            g_cti[NCAND];
__device__ float          g_cbv[NCAND];
__device__ int            g_cbi[NCAND];
__device__ int            g_ids[16];

// ============================ helpers ======================================
__device__ __forceinline__ uint32_t smem_u32(const void* p) {
    uint32_t a;
    asm("{ .reg .u64 t; cvta.to.shared.u64 t, %1; cvt.u32.u64 %0, t; }" : "=r"(a) : "l"(p));
    return a;
}
__device__ __forceinline__ void split2(float x, float y, uint32_t& hi, uint32_t& lo)
{
    __nv_bfloat16 hx = __float2bfloat16(x);
    __nv_bfloat16 hy = __float2bfloat16(y);
    __nv_bfloat16 lx = __float2bfloat16(x - __bfloat162float(hx));
    __nv_bfloat16 ly = __float2bfloat16(y - __bfloat162float(hy));
    hi = (uint32_t)__bfloat16_as_ushort(hx) | ((uint32_t)__bfloat16_as_ushort(hy) << 16);
    lo = (uint32_t)__bfloat16_as_ushort(lx) | ((uint32_t)__bfloat16_as_ushort(ly) << 16);
}
__device__ __forceinline__ void mma_bf16(float* d, const uint32_t* a, const uint32_t* b)
{
    asm("mma.sync.aligned.m16n8k16.row.col.f32.bf16.bf16.f32 "
        "{%0,%1,%2,%3}, {%4,%5,%6,%7}, {%8,%9}, {%0,%1,%2,%3};"
        : "+f"(d[0]), "+f"(d[1]), "+f"(d[2]), "+f"(d[3])
        : "r"(a[0]), "r"(a[1]), "r"(a[2]), "r"(a[3]), "r"(b[0]), "r"(b[1]));
}
#define LDSM_X4(r0, r1, r2, r3, addr) \
    asm volatile("ldmatrix.sync.aligned.m8n8.x4.shared.b16 {%0,%1,%2,%3}, [%4];" \
                 : "=r"(r0), "=r"(r1), "=r"(r2), "=r"(r3) : "r"(addr))
#define CP_ASYNC16(dst, src, sz) \
    asm volatile("cp.async.cg.shared.global [%0], [%1], 16, %2;" \
                 :: "r"(dst), "l"(src), "r"(sz))
#define CP_COMMIT()  asm volatile("cp.async.commit_group;" ::: "memory")
#define CP_WAIT(n)   asm volatile("cp.async.wait_group %0;" :: "n"(n) : "memory")

__device__ __forceinline__ float fast_sigmoid(float x) {
    return __fdividef(1.f, 1.f + __expf(-x));
}
__device__ __forceinline__ float fast_tanh(float x) {
    return __fdividef(2.f, 1.f + __expf(-2.f * x)) - 1.f;
}
__device__ __forceinline__ bool tk_better(float v1, int i1, float v2, int i2, bool mx)
{
    if (mx) return (v1 > v2) || (v1 == v2 && i1 < i2);
    return (v1 < v2) || (v1 == v2 && i1 < i2);
}

// ================= weight convert kernel (w1 + wab only) ===================
#define NBW1 (DH * DIN / 4 / 256)               // 512
#define NBWAB (DH * DH / 4 / 256)               // 256
__global__ __launch_bounds__(256) void conv_w_kernel(
    const float* __restrict__ fcW,
    const float* __restrict__ Wa, const float* __restrict__ Wb,
    __nv_bfloat16* __restrict__ w1hi, __nv_bfloat16* __restrict__ w1lo)
{
    int b = blockIdx.x;
    if (b < NBW1) {
        int i = b * 256 + threadIdx.x;
        float4 v = ((const float4*)fcW)[i];
        uint32_t h0, l0, h1, l1;
        split2(v.x, v.y, h0, l0);
        split2(v.z, v.w, h1, l1);
        ((uint2*)w1hi)[i] = make_uint2(h0, h1);
        ((uint2*)w1lo)[i] = make_uint2(l0, l1);
    } else {
        int i = (b - NBW1) * 256 + threadIdx.x;
        int elem = i * 4;
        int row = elem / DH;
        int col = elem % DH;
        const float* src = (row < DA) ? &Wa[(size_t)row * DH + col]
                                      : &Wb[(size_t)(row - DA) * DH + col];
        float4 v = *(const float4*)src;
        uint32_t h0, l0, h1, l1;
        split2(v.x, v.y, h0, l0);
        split2(v.z, v.w, h1, l1);
        ((uint2*)g_wab_hi)[i] = make_uint2(h0, h1);
        ((uint2*)g_wab_lo)[i] = make_uint2(l0, l1);
    }
}

// ===========================================================================
// 3xBF16 split GEMM (frozen R8 mainloop; R15 structure)
// ===========================================================================
__global__ __launch_bounds__(256, 2) void gemm_mma_kernel(
    const float* __restrict__ Xraw,
    const __nv_bfloat16* __restrict__ Ahi, const __nv_bfloat16* __restrict__ Alo,
    const __nv_bfloat16* __restrict__ Bhi, const __nv_bfloat16* __restrict__ Blo,
    const float* __restrict__ bias,
    const float* __restrict__ abv, const float* __restrict__ bbv,
    const float* __restrict__ cWv, const float* __restrict__ clsW,
    int K, int mode)
{
    extern __shared__ char smem[];
    const uint32_t sbase = smem_u32(smem);

    const int tid    = threadIdx.x;
    const int wid    = tid >> 5;
    const int lane   = tid & 31;
    const int warp_m = wid & 1;
    const int warp_n = wid >> 1;
    const int g      = lane >> 2;
    const int t      = lane & 3;
    const int bx     = blockIdx.x;
    const int row0   = blockIdx.y * BM;
    const int col0   = (mode == 0) ? bx * BN : bx * 64;

    const int mat   = lane >> 3;
    const int rowin = lane & 7;
    const int rowA  = warp_m * 64 + ((mat & 1) << 3) + rowin;
    const int kA    = (mat >> 1) << 3;
    const int rowB0 = warp_n * 32 + ((mat >> 1) << 3) + rowin;
    const int kB    = (mat & 1) << 3;

    const int frow = tid >> 2;
    const int fseg = (tid & 3) * 16;

    float acc[4][4][4];
#pragma unroll
    for (int mt = 0; mt < 4; mt++)
#pragma unroll
        for (int nt = 0; nt < 4; nt++)
#pragma unroll
            for (int e = 0; e < 4; e++) acc[mt][nt][e] = 0.f;

    const int KT = K / BK;

    auto fill = [&](int kt, int s) {
        if (mode == 0) {
            uint32_t xb = sbase + OFF_XRAW + s * XSTAGE;
#pragma unroll
            for (int i = 0; i < 4; i++) {
                int c   = tid + 256 * i;
                int r   = c >> 3;
                int seg = (c & 7) * 16;
                int gr  = row0 + r;
                uint32_t ok = (gr < NROWS) ? 16u : 0u;
                const float* src = &Xraw[(size_t)min(gr, NROWS - 1) * K + kt * BK + (seg >> 2)];
                CP_ASYNC16(xb + XSW(r, seg), (const char*)src, ok);
            }
            uint32_t sb = sbase + s * STAGEB;
            int kc = kt * BK + (fseg >> 1);
#pragma unroll
            for (int i = 0; i < 2; i++) {
                int r = frow + 64 * i;
                int brow = col0 + r;
                size_t bi = (size_t)brow * K + kc;
                uint32_t d = sb + r * ROWB + fseg;
                CP_ASYNC16(d + OFF_BHI, (const char*)&Bhi[bi], 16u);
                CP_ASYNC16(d + OFF_BLO, (const char*)&Blo[bi], 16u);
            }
        } else {
            uint32_t sb = sbase + s * STAGEB;
            int kc = kt * BK + (fseg >> 1);
#pragma unroll
            for (int i = 0; i < 2; i++) {
                int r = frow + 64 * i;
                int gr = row0 + r;
                uint32_t ok = (gr < NROWS) ? 16u : 0u;
                size_t gi = (size_t)min(gr, NROWS - 1) * K + kc;
                uint32_t d = sb + r * ROWB + fseg;
                CP_ASYNC16(d + OFF_AHI, (const char*)&Ahi[gi], ok);
                CP_ASYNC16(d + OFF_ALO, (const char*)&Alo[gi], ok);
                int w = r >> 5, ii = r & 31;
                int j = col0 + (w << 4) + (ii & 15);
                int brow = (ii < 16) ? j : j + DA;
                size_t bi = (size_t)brow * K + kc;
                CP_ASYNC16(d + OFF_BHI, (const char*)&Bhi[bi], 16u);
                CP_ASYNC16(d + OFF_BLO, (const char*)&Blo[bi], 16u);
            }
        }
    };

    fill(0, 0);
    CP_COMMIT();

    for (int kt = 0; kt < KT; kt++) {
        int cur = kt & 1;
        if (kt + 1 < KT) {
            fill(kt + 1, cur ^ 1);
            CP_COMMIT();
            CP_WAIT(1);
        } else {
            CP_WAIT(0);
        }
        __syncthreads();

        uint32_t sb = sbase + cur * STAGEB;

        if (mode == 0) {
            int r  = tid >> 1;
            int hf = tid & 1;
            const char* xbase = smem + OFF_XRAW + cur * XSTAGE;
            float4 v0 = *(const float4*)(xbase + XSW(r, hf * 64 + 0));
            float4 v1 = *(const float4*)(xbase + XSW(r, hf * 64 + 16));
            float4 v2 = *(const float4*)(xbase + XSW(r, hf * 64 + 32));
            float4 v3 = *(const float4*)(xbase + XSW(r, hf * 64 + 48));
            uint32_t h0, l0, h1, l1, h2, l2, h3, l3, h4, l4, h5, l5, h6, l6, h7, l7;
            split2(v0.x, v0.y, h0, l0); split2(v0.z, v0.w, h1, l1);
            split2(v1.x, v1.y, h2, l2); split2(v1.z, v1.w, h3, l3);
            split2(v2.x, v2.y, h4, l4); split2(v2.z, v2.w, h5, l5);
            split2(v3.x, v3.y, h6, l6); split2(v3.z, v3.w, h7, l7);
            char* dA = smem + cur * STAGEB + r * ROWB + hf * 32;
            *(uint4*)(dA + OFF_AHI)      = make_uint4(h0, h1, h2, h3);
            *(uint4*)(dA + OFF_AHI + 16) = make_uint4(h4, h5, h6, h7);
            *(uint4*)(dA + OFF_ALO)      = make_uint4(l0, l1, l2, l3);
            *(uint4*)(dA + OFF_ALO + 16) = make_uint4(l4, l5, l6, l7);
            __syncthreads();
        }

#pragma unroll
        for (int ks = 0; ks < BK; ks += 16) {
            uint32_t bh[4][2], bl[4][2];
#pragma unroll
            for (int p = 0; p < 2; p++) {
                uint32_t ab_ = sb + (rowB0 + p * 16) * ROWB + (ks + kB) * 2;
                LDSM_X4(bh[2 * p][0], bh[2 * p][1], bh[2 * p + 1][0], bh[2 * p + 1][1],
                        ab_ + OFF_BHI);
                LDSM_X4(bl[2 * p][0], bl[2 * p][1], bl[2 * p + 1][0], bl[2 * p + 1][1],
                        ab_ + OFF_BLO);
            }
#pragma unroll
            for (int mt = 0; mt < 4; mt++) {
                uint32_t aa = sb + (rowA + mt * 16) * ROWB + (ks + kA) * 2;
                uint32_t ah[4], al[4];
                LDSM_X4(ah[0], ah[1], ah[2], ah[3], aa + OFF_AHI);
                LDSM_X4(al[0], al[1], al[2], al[3], aa + OFF_ALO);
#pragma unroll
                for (int nt = 0; nt < 4; nt++) mma_bf16(acc[mt][nt], ah, bh[nt]);
#pragma unroll
                for (int nt = 0; nt < 4; nt++) mma_bf16(acc[mt][nt], ah, bl[nt]);
#pragma unroll
                for (int nt = 0; nt < 4; nt++) mma_bf16(acc[mt][nt], al, bh[nt]);
            }
        }
        __syncthreads();
    }

    if (mode == 0) {
        float* sc0 = (float*)smem;
        float* sc1 = (float*)smem + 512;
#pragma unroll
        for (int mt = 0; mt < 4; mt++) {
            int r0 = row0 + warp_m * 64 + mt * 16 + g;
            int r1 = r0 + 8;
            float p00 = 0.f, p01 = 0.f, p10 = 0.f, p11 = 0.f;
#pragma unroll
            for (int nt = 0; nt < 4; nt++) {
                int c = col0 + warp_n * 32 + nt * 8 + 2 * t;
                float b0 = __ldg(&bias[c]), b1 = __ldg(&bias[c + 1]);
                float v0 = fmaxf(acc[mt][nt][0] + b0, 0.f);
                float v1 = fmaxf(acc[mt][nt][1] + b1, 0.f);
                float v2 = fmaxf(acc[mt][nt][2] + b0, 0.f);
                float v3 = fmaxf(acc[mt][nt][3] + b1, 0.f);
                float w00 = __ldg(&clsW[c]),      w01 = __ldg(&clsW[c + 1]);
                float w10 = __ldg(&clsW[DH + c]), w11 = __ldg(&clsW[DH + c + 1]);
                p00 += v0 * w00 + v1 * w01;
                p01 += v0 * w10 + v1 * w11;
                p10 += v2 * w00 + v3 * w01;
                p11 += v2 * w10 + v3 * w11;
                uint32_t hh, ll;
                if (r0 < NROWS) {
                    split2(v0, v1, hh, ll);
                    *(uint32_t*)&g_hh_hi[(size_t)r0 * DH + c] = hh;
                    *(uint32_t*)&g_hh_lo[(size_t)r0 * DH + c] = ll;
                }
                if (r1 < NROWS) {
                    split2(v2, v3, hh, ll);
                    *(uint32_t*)&g_hh_hi[(size_t)r1 * DH + c] = hh;
                    *(uint32_t*)&g_hh_lo[(size_t)r1 * DH + c] = ll;
                }
            }
            p00 += __shfl_xor_sync(0xffffffffu, p00, 1);
            p00 += __shfl_xor_sync(0xffffffffu, p00, 2);
            p01 += __shfl_xor_sync(0xffffffffu, p01, 1);
            p01 += __shfl_xor_sync(0xffffffffu, p01, 2);
            p10 += __shfl_xor_sync(0xffffffffu, p10, 1);
            p10 += __shfl_xor_sync(0xffffffffu, p10, 2);
            p11 += __shfl_xor_sync(0xffffffffu, p11, 1);
            p11 += __shfl_xor_sync(0xffffffffu, p11, 2);
            if (t == 0) {
                int rl = warp_m * 64 + mt * 16 + g;
                sc0[rl * 4 + warp_n] = p00;
                sc1[rl * 4 + warp_n] = p01;
                sc0[(rl + 8) * 4 + warp_n] = p10;
                sc1[(rl + 8) * 4 + warp_n] = p11;
            }
        }
        __syncthreads();
        if (tid < 128) {
            int grow = row0 + tid;
            if (grow < NROWS) {
                g_cls_part[bx][grow][0] = sc0[tid * 4 + 0] + sc0[tid * 4 + 1] +
                                          sc0[tid * 4 + 2] + sc0[tid * 4 + 3];
                g_cls_part[bx][grow][1] = sc1[tid * 4 + 0] + sc1[tid * 4 + 1] +
                                          sc1[tid * 4 + 2] + sc1[tid * 4 + 3];
            }
        }
    } else {
        float* spart = (float*)smem;
#pragma unroll
        for (int mt = 0; mt < 4; mt++) {
            float s0 = 0.f, s1 = 0.f;
#pragma unroll
            for (int nt = 0; nt < 2; nt++) {
                int j = col0 + warp_n * 16 + nt * 8 + 2 * t;
                float ab0 = __ldg(&abv[j]), ab1 = __ldg(&abv[j + 1]);
                float bb0 = __ldg(&bbv[j]), bb1 = __ldg(&bbv[j + 1]);
                float c0  = __ldg(&cWv[j]), c1  = __ldg(&cWv[j + 1]);
                s0 += c0 * fast_tanh(acc[mt][nt][0] + ab0) * fast_sigmoid(acc[mt][nt + 2][0] + bb0);
                s0 += c1 * fast_tanh(acc[mt][nt][1] + ab1) * fast_sigmoid(acc[mt][nt + 2][1] + bb1);
                s1 += c0 * fast_tanh(acc[mt][nt][2] + ab0) * fast_sigmoid(acc[mt][nt + 2][2] + bb0);
                s1 += c1 * fast_tanh(acc[mt][nt][3] + ab1) * fast_sigmoid(acc[mt][nt + 2][3] + bb1);
            }
            s0 += __shfl_xor_sync(0xffffffffu, s0, 1);
            s0 += __shfl_xor_sync(0xffffffffu, s0, 2);
            s1 += __shfl_xor_sync(0xffffffffu, s1, 1);
            s1 += __shfl_xor_sync(0xffffffffu, s1, 2);
            if (t == 0) {
                int rl = warp_m * 64 + mt * 16 + g;
                spart[rl * 4 + warp_n] = s0;
                spart[(rl + 8) * 4 + warp_n] = s1;
            }
        }
        __syncthreads();
        if (tid < 128) {
            int grow = row0 + tid;
            if (grow < NROWS) {
                g_part[bx][grow] = spart[tid * 4 + 0] + spart[tid * 4 + 1] +
                                   spart[tid * 4 + 2] + spart[tid * 4 + 3];
            }
        }
    }
}

// ---------------------------------------------------------------------------
// post1: Araw + IS finalize + softmax partials + block top8/bottom8 (R15 ver)
// ---------------------------------------------------------------------------
__global__ __launch_bounds__(256) void post1_kernel(
    const float* __restrict__ cb, const float* __restrict__ clsb,
    float* __restrict__ Araw, float* __restrict__ IS)
{
    __shared__ float wred[8][4];
    __shared__ float cwv[64];
    __shared__ int   cwi[64];
    int tid  = threadIdx.x;
    int wrp  = tid >> 5;
    int lane = tid & 31;
    int n    = blockIdx.x * 256 + tid;
    bool valid = (n < NROWS);

    float a = -INFINITY, is0 = 0.f, is1 = 0.f;
    if (valid) {
        a = cb[0] + g_part[0][n] + g_part[1][n] + g_part[2][n] + g_part[3][n];
        Araw[n] = a;
        is0 = clsb[0] + g_cls_part[0][n][0] + g_cls_part[1][n][0] +
                        g_cls_part[2][n][0] + g_cls_part[3][n][0];
        is1 = clsb[1] + g_cls_part[0][n][1] + g_cls_part[1][n][1] +
                        g_cls_part[2][n][1] + g_cls_part[3][n][1];
        IS[(size_t)n * 2 + 0] = is0;
        IS[(size_t)n * 2 + 1] = is1;
    }

    float wm = a;
#pragma unroll
    for (int m = 16; m > 0; m >>= 1) wm = fmaxf(wm, __shfl_xor_sync(0xffffffffu, wm, m));
    if (lane == 0) wred[wrp][0] = wm;
    __syncthreads();
    float bm = wred[0][0];
#pragma unroll
    for (int i = 1; i < 8; i++) bm = fmaxf(bm, wred[i][0]);

    float e  = valid ? expf(a - bm) : 0.f;
    float p0 = e * is0, p1 = e * is1;
#pragma unroll
    for (int m = 16; m > 0; m >>= 1) {
        e  += __shfl_xor_sync(0xffffffffu, e,  m);
        p0 += __shfl_xor_sync(0xffffffffu, p0, m);
        p1 += __shfl_xor_sync(0xffffffffu, p1, m);
    }
    if (lane == 0) { wred[wrp][1] = e; wred[wrp][2] = p0; wred[wrp][3] = p1; }
    __syncthreads();
    if (tid == 0) {
        float se = 0.f, s0 = 0.f, s1 = 0.f;
#pragma unroll
        for (int i = 0; i < 8; i++) { se += wred[i][1]; s0 += wred[i][2]; s1 += wred[i][3]; }
        g_red[blockIdx.x][0] = bm;
        g_red[blockIdx.x][1] = se;
        g_red[blockIdx.x][2] = s0;
        g_red[blockIdx.x][3] = s1;
    }

    for (int pass = 0; pass < 2; pass++) {
        bool mx = (pass == 0);
        float cv = valid ? a : (mx ? -INFINITY : INFINITY);
        int   ci = valid ? n : 0x7fffffff;
        for (int it = 0; it < 8; it++) {
            float bv = cv;
            int   bi = ci;
#pragma unroll
            for (int m = 16; m > 0; m >>= 1) {
                float ov = __shfl_xor_sync(0xffffffffu, bv, m);
                int   oi = __shfl_xor_sync(0xffffffffu, bi, m);
                if (tk_better(ov, oi, bv, bi, mx)) { bv = ov; bi = oi; }
            }
            if (lane == it) { cwv[wrp * 8 + it] = bv; cwi[wrp * 8 + it] = bi; }
            if (ci == bi) cv = mx ? -INFINITY : INFINITY;
        }
        __syncthreads();
        if (wrp == 0) {
            float e0 = cwv[lane], e1 = cwv[32 + lane];
            int   i0 = cwi[lane], i1 = cwi[32 + lane];
            for (int it = 0; it < 8; it++) {
                float bv = e0; int bi = i0;
                if (tk_better(e1, i1, bv, bi, mx)) { bv = e1; bi = i1; }
#pragma unroll
                for (int m = 16; m > 0; m >>= 1) {
                    float ov = __shfl_xor_sync(0xffffffffu, bv, m);
                    int   oi = __shfl_xor_sync(0xffffffffu, bi, m);
                    if (tk_better(ov, oi, bv, bi, mx)) { bv = ov; bi = oi; }
                }
                if (lane == 0) {
                    if (mx) { g_ctv[blockIdx.x * 8 + it] = bv; g_cti[blockIdx.x * 8 + it] = bi; }
                    else    { g_cbv[blockIdx.x * 8 + it] = bv; g_cbi[blockIdx.x * 8 + it] = bi; }
                }
                if (i0 == bi)      e0 = mx ? -INFINITY : INFINITY;
                else if (i1 == bi) e1 = mx ? -INFINITY : INFINITY;
            }
        }
        __syncthreads();
    }
}

// ---------------------------------------------------------------------------
// tail: barrier-light preds + register-resident candidate merge + loss
// ---------------------------------------------------------------------------
__global__ __launch_bounds__(512) void tail_kernel(
    const float* __restrict__ iW, const float* __restrict__ ib,
    float* __restrict__ preds, float* __restrict__ loss)
{
    __shared__ float wred[16][4];
    __shared__ float cw[128];
    __shared__ int   cwI[128];
    __shared__ int   sel[16];
    __shared__ float ls[16];
    int tid  = threadIdx.x;
    int wrp  = tid >> 5;
    int lane = tid & 31;

    // ---- preds: warp-shuffle partials over 196 blocks (2 barriers) ----
    float m = (tid < NB_POST) ? g_red[tid][0] : -INFINITY;
    float wm = m;
#pragma unroll
    for (int k = 16; k > 0; k >>= 1) wm = fmaxf(wm, __shfl_xor_sync(0xffffffffu, wm, k));
    if (lane == 0) wred[wrp][0] = wm;
    __syncthreads();
    float M = wred[0][0];
#pragma unroll
    for (int i = 1; i < 16; i++) M = fmaxf(M, wred[i][0]);

    float se = 0.f, s0 = 0.f, s1 = 0.f;
    if (tid < NB_POST) {
        float w = expf(g_red[tid][0] - M);
        se = w * g_red[tid][1];
        s0 = w * g_red[tid][2];
        s1 = w * g_red[tid][3];
    }
#pragma unroll
    for (int k = 16; k > 0; k >>= 1) {
        se += __shfl_xor_sync(0xffffffffu, se, k);
        s0 += __shfl_xor_sync(0xffffffffu, s0, k);
        s1 += __shfl_xor_sync(0xffffffffu, s1, k);
    }
    if (lane == 0) { wred[wrp][1] = se; wred[wrp][2] = s0; wred[wrp][3] = s1; }
    __syncthreads();
    if (tid == 0) {
        float tse = 0.f, ts0 = 0.f, ts1 = 0.f;
#pragma unroll
        for (int i = 0; i < 16; i++) { tse += wred[i][1]; ts0 += wred[i][2]; ts1 += wred[i][3]; }
        preds[0] = ts0 / tse;
        preds[1] = ts1 / tse;
    }

    // ---- candidate merge: 16 warps x 98 candidates, register-resident ----
    for (int pass = 0; pass < 2; pass++) {
        bool mx = (pass == 0);
        float pad = mx ? -INFINITY : INFINITY;
        const float* cvsrc = mx ? g_ctv : g_cbv;
        const int*   cisrc = mx ? g_cti : g_cbi;
        int base = wrp * NC_PER_WARP;
        float v[4]; int ix[4];
#pragma unroll
        for (int j = 0; j < 4; j++) {
            int i = base + lane + 32 * j;
            bool ok = (lane + 32 * j) < NC_PER_WARP;
            v[j]  = ok ? cvsrc[i] : pad;
            ix[j] = ok ? cisrc[i] : 0x7fffffff;
        }
        // warp-local 8 extractions (no barriers)
        for (int it = 0; it < 8; it++) {
            float bv = v[0]; int bi = ix[0];
#pragma unroll
            for (int j = 1; j < 4; j++)
                if (tk_better(v[j], ix[j], bv, bi, mx)) { bv = v[j]; bi = ix[j]; }
#pragma unroll
            for (int k = 16; k > 0; k >>= 1) {
                float ov = __shfl_xor_sync(0xffffffffu, bv, k);
                int   oi = __shfl_xor_sync(0xffffffffu, bi, k);
                if (tk_better(ov, oi, bv, bi, mx)) { bv = ov; bi = oi; }
            }
            if (lane == it) { cw[wrp * 8 + it] = bv; cwI[wrp * 8 + it] = bi; }
#pragma unroll
            for (int j = 0; j < 4; j++)
                if (ix[j] == bi) { v[j] = pad; ix[j] = 0x7fffffff; }
        }
        __syncthreads();
        // warp 0 merges 128 -> 8 (each lane owns 4 entries)
        if (wrp == 0) {
            float e0 = cw[lane],      e1 = cw[32 + lane];
            float e2 = cw[64 + lane], e3 = cw[96 + lane];
            int   i0 = cwI[lane],      i1 = cwI[32 + lane];
            int   i2 = cwI[64 + lane], i3 = cwI[96 + lane];
            for (int it = 0; it < 8; it++) {
                float bv = e0; int bi = i0;
                if (tk_better(e1, i1, bv, bi, mx)) { bv = e1; bi = i1; }
                if (tk_better(e2, i2, bv, bi, mx)) { bv = e2; bi = i2; }
                if (tk_better(e3, i3, bv, bi, mx)) { bv = e3; bi = i3; }
#pragma unroll
                for (int k = 16; k > 0; k >>= 1) {
                    float ov = __shfl_xor_sync(0xffffffffu, bv, k);
                    int   oi = __shfl_xor_sync(0xffffffffu, bi, k);
                    if (tk_better(ov, oi, bv, bi, mx)) { bv = ov; bi = oi; }
                }
                if (lane == 0) { sel[pass * 8 + it] = bi; g_ids[pass * 8 + it] = bi; }
                if (i0 == bi)      { e0 = pad; i0 = 0x7fffffff; }
                else if (i1 == bi) { e1 = pad; i1 = 0x7fffffff; }
                else if (i2 == bi) { e2 = pad; i2 = 0x7fffffff; }
                else if (i3 == bi) { e3 = pad; i3 = 0x7fffffff; }
            }
        }
        __syncthreads();
    }

    // ---- instance loss: 16 warps, one selected row each ----
    int id = sel[wrp];
    const __nv_bfloat16* hhi = &g_hh_hi[(size_t)id * DH];
    const __nv_bfloat16* hlo = &g_hh_lo[(size_t)id * DH];
    float c0 = 0.f, c1 = 0.f;
    for (int k = lane * 4; k < DH; k += 128) {
        uint2 ph = *(const uint2*)&hhi[k];
        uint2 pl = *(const uint2*)&hlo[k];
        float h0 = __bfloat162float(__ushort_as_bfloat16((unsigned short)(ph.x & 0xffff)))
                 + __bfloat162float(__ushort_as_bfloat16((unsigned short)(pl.x & 0xffff)));
        float h1 = __bfloat162float(__ushort_as_bfloat16((unsigned short)(ph.x >> 16)))
                 + __bfloat162float(__ushort_as_bfloat16((unsigned short)(pl.x >> 16)));
        float h2 = __bfloat162float(__ushort_as_bfloat16((unsigned short)(ph.y & 0xffff)))
                 + __bfloat162float(__ushort_as_bfloat16((unsigned short)(pl.y & 0xffff)));
        float h3 = __bfloat162float(__ushort_as_bfloat16((unsigned short)(ph.y >> 16)))
                 + __bfloat162float(__ushort_as_bfloat16((unsigned short)(pl.y >> 16)));
        float4 w0 = *(const float4*)&iW[k];
        float4 w1 = *(const float4*)&iW[DH + k];
        c0 += h0 * w0.x + h1 * w0.y + h2 * w0.z + h3 * w0.w;
        c1 += h0 * w1.x + h1 * w1.y + h2 * w1.z + h3 * w1.w;
    }
#pragma unroll
    for (int mk = 16; mk > 0; mk >>= 1) {
        c0 += __shfl_xor_sync(0xffffffffu, c0, mk);
        c1 += __shfl_xor_sync(0xffffffffu, c1, mk);
    }
    if (lane == 0) {
        float l0 = c0 + ib[0], l1 = c1 + ib[1];
        float mm  = fmaxf(l0, l1);
        float lse = mm + logf(expf(l0 - mm) + expf(l1 - mm));
        float lt  = (wrp < KSEL) ? l1 : l0;
        ls[wrp] = lse - lt;
    }
    __syncthreads();
    if (tid == 0) {
        float tsum = 0.f;
        for (int i = 0; i < 16; i++) tsum += ls[i];
        loss[0] = tsum / 16.f;
    }
}

// ---------------------------------------------------------------------------
extern "C" void kernel_launch(void* const* d_in, const int* in_sizes, int n_in,
                              void* d_out, int out_size)
{
    const float* h     = (const float*)d_in[0];
    const float* fcW   = (const float*)d_in[1];
    const float* fcb   = (const float*)d_in[2];
    const float* aW    = (const float*)d_in[3];
    const float* abv   = (const float*)d_in[4];
    const float* bW    = (const float*)d_in[5];
    const float* bbv   = (const float*)d_in[6];
    const float* cWv   = (const float*)d_in[7];
    const float* cbv   = (const float*)d_in[8];
    const float* clsW  = (const float*)d_in[9];
    const float* clsb  = (const float*)d_in[10];
    const float* instW = (const float*)d_in[11];
    const float* instb = (const float*)d_in[12];

    float* out   = (float*)d_out;
    float* preds = out;
    float* IS    = out + 2;
    float* Araw  = out + 2 + 2 * NROWS;
    float* loss  = out + 2 + 3 * NROWS;

    static int inited = 0;
    if (!inited) {
        cudaFuncSetAttribute(gemm_mma_kernel,
                             cudaFuncAttributeMaxDynamicSharedMemorySize, SMEM_GEMM);
        inited = 1;
    }

    __nv_bfloat16 *w1hi, *w1lo, *wabhi, *wablo, *hhhi, *hhlo;
    cudaGetSymbolAddress((void**)&w1hi,  g_w1_hi);
    cudaGetSymbolAddress((void**)&w1lo,  g_w1_lo);
    cudaGetSymbolAddress((void**)&wabhi, g_wab_hi);
    cudaGetSymbolAddress((void**)&wablo, g_wab_lo);
    cudaGetSymbolAddress((void**)&hhhi,  g_hh_hi);
    cudaGetSymbolAddress((void**)&hhlo,  g_hh_lo);

    conv_w_kernel<<<NBW1 + NBWAB, 256>>>(fcW, aW, bW, w1hi, w1lo);

    dim3 grid(4, (NROWS + BM - 1) / BM);

    gemm_mma_kernel<<<grid, 256, SMEM_GEMM>>>(h, (const __nv_bfloat16*)0,
                                              (const __nv_bfloat16*)0,
                                              w1hi, w1lo, fcb,
                                              (const float*)0, (const float*)0,
                                              (const float*)0, clsW, DIN, 0);

    gemm_mma_kernel<<<grid, 256, SMEM_GEMM>>>((const float*)0, hhhi, hhlo,
                                              wabhi, wablo,
                                              (const float*)0, abv, bbv, cWv,
                                              (const float*)0, DH, 1);

    post1_kernel<<<NB_POST, 256>>>(cbv, clsb, Araw, IS);

    tail_kernel<<<1, 512>>>(instW, instb, preds, loss);
}